// round 1
// baseline (speedup 1.0000x reference)
#include <cuda_runtime.h>
#include <cstddef>

#define DIM 512
#define HID 2048
#define NBR 512
#define ND (NBR*DIM)
#define NSTEPS 8
#define SUBSTEPS 2

// ---------------- device scratch (static allocation, allowed) ----------------
__device__ float g_y[DIM];
__device__ float g_Dy[ND];
__device__ float g_a[HID];
__device__ float g_kdy[4*DIM];
__device__ float g_kDy[16*ND];      // [stage*4 + ksplit][ND]  (split-K partials)
__device__ float g_G[NBR*HID];

typedef unsigned long long u64;

// ---------------- packed f32x2 helpers (Blackwell FFMA2) ----------------
__device__ __forceinline__ u64 pack2(float lo, float hi) {
    u64 r; asm("mov.b64 %0, {%1, %2};" : "=l"(r) : "f"(lo), "f"(hi)); return r;
}
__device__ __forceinline__ u64 fma2(u64 a, u64 b, u64 c) {
    u64 d; asm("fma.rn.f32x2 %0, %1, %2, %3;" : "=l"(d) : "l"(a), "l"(b), "l"(c)); return d;
}
__device__ __forceinline__ float2 unpack2(u64 v) {
    float lo, hi; asm("mov.b64 {%0, %1}, %2;" : "=f"(lo), "=f"(hi) : "l"(v));
    return make_float2(lo, hi);
}

__device__ __forceinline__ float4 axpy4(float4 v, float c, float4 a, float4 b, float4 d, float4 e) {
    v.x += c*(a.x+b.x+d.x+e.x); v.y += c*(a.y+b.y+d.y+e.y);
    v.z += c*(a.z+b.z+d.z+e.z); v.w += c*(a.w+b.w+d.w+e.w);
    return v;
}

// ---------------- SGEMM 64x128 tile, 128 thr, 8x8 microtile on f32x2 ----------------
// C[M=512 x N] = A[512 x K] * B[K x N]  (all row-major), K covered per-z as k0..k0+512
// AXPY:  A_eff = A + c*(P0+P1+P2+P3)   (fused RK4 stage prep over split-K partials)
// EPI_G: out = s*u*(1 - a*u), s = 1-a^2, per-column a = avec[col]  (Jv + 0.5Hvv epilogue)
template<bool AXPY, bool EPI_G>
__global__ void __launch_bounds__(128)
gemm64x128(const float* __restrict__ A, int lda,
           const float* __restrict__ P0, const float* __restrict__ P1,
           const float* __restrict__ P2, const float* __restrict__ P3,
           const float* __restrict__ ts, int interval, float cmul,
           const float* __restrict__ B, int ldb,
           const float* __restrict__ avec,
           float* __restrict__ Cbase, int ldc, int zstride)
{
    constexpr int KSUB = 512;
    __shared__ float As[2][16][64];    // transposed A tile (k-major)
    __shared__ float Bs[2][16][128];

    const int t  = threadIdx.x;
    const int rb = blockIdx.y * 64;
    const int cb = blockIdx.x * 128;
    const int z  = blockIdx.z;
    const int k0 = z * KSUB;
    float* __restrict__ C = Cbase + (size_t)z * zstride;

    float c = 0.f;
    if (AXPY) {
        float dt = (ts[interval+1] - ts[interval]) * (1.0f / SUBSTEPS);
        c = cmul * dt;
    }

    // A loader: thread t -> row (t&63), k-group ((t>>6)*8), 2 float4 per tile
    const int ar  = t & 63;
    const int akg = (t >> 6) * 8;
    const float* Arow = A + (size_t)(rb + ar) * lda + k0 + akg;
    const float *Q0 = nullptr, *Q1 = nullptr, *Q2 = nullptr, *Q3 = nullptr;
    if (AXPY) {
        size_t off = (size_t)(rb + ar) * lda + k0 + akg;  // partials share lda=512
        Q0 = P0 + off; Q1 = P1 + off; Q2 = P2 + off; Q3 = P3 + off;
    }
    // B loader: thread t -> rows (t>>5)+4i, float4 col (t&31); coalesced 512B/warp
    const int brw = t >> 5;
    const int bc4 = t & 31;
    const float* Bp = B + (size_t)(k0 + brw) * ldb + cb + bc4 * 4;

    const int ty = t >> 4;   // 0..7  -> rows ty*4..+3 and ty*4+32..+35
    const int tx = t & 15;   // 0..15 -> cols tx*4..+3 and 64+tx*4..+67

    u64 acc[8][4];
    #pragma unroll
    for (int r = 0; r < 8; r++)
        #pragma unroll
        for (int j = 0; j < 4; j++) acc[r][j] = 0ull;

    float4 sa0, sa1, sp[4][2], sb[4];

    auto ldg_tile = [&](int kc) {
        sa0 = *(const float4*)(Arow + kc);
        sa1 = *(const float4*)(Arow + kc + 4);
        if (AXPY) {
            sp[0][0] = *(const float4*)(Q0 + kc); sp[0][1] = *(const float4*)(Q0 + kc + 4);
            sp[1][0] = *(const float4*)(Q1 + kc); sp[1][1] = *(const float4*)(Q1 + kc + 4);
            sp[2][0] = *(const float4*)(Q2 + kc); sp[2][1] = *(const float4*)(Q2 + kc + 4);
            sp[3][0] = *(const float4*)(Q3 + kc); sp[3][1] = *(const float4*)(Q3 + kc + 4);
        }
        #pragma unroll
        for (int i = 0; i < 4; i++)
            sb[i] = *(const float4*)(Bp + (size_t)(kc + 4*i) * ldb);
    };
    auto sts_tile = [&](int buf) {
        float4 v0 = sa0, v1 = sa1;
        if (AXPY) {
            v0 = axpy4(v0, c, sp[0][0], sp[1][0], sp[2][0], sp[3][0]);
            v1 = axpy4(v1, c, sp[0][1], sp[1][1], sp[2][1], sp[3][1]);
        }
        As[buf][akg+0][ar] = v0.x; As[buf][akg+1][ar] = v0.y;
        As[buf][akg+2][ar] = v0.z; As[buf][akg+3][ar] = v0.w;
        As[buf][akg+4][ar] = v1.x; As[buf][akg+5][ar] = v1.y;
        As[buf][akg+6][ar] = v1.z; As[buf][akg+7][ar] = v1.w;
        #pragma unroll
        for (int i = 0; i < 4; i++)
            *(float4*)&Bs[buf][brw + 4*i][bc4*4] = sb[i];
    };
    auto compute = [&](int buf) {
        #pragma unroll
        for (int k = 0; k < 16; k++) {
            float4 a0 = *(const float4*)&As[buf][k][ty*4];
            float4 a1 = *(const float4*)&As[buf][k][ty*4 + 32];
            float4 b0 = *(const float4*)&Bs[buf][k][tx*4];
            float4 b1 = *(const float4*)&Bs[buf][k][64 + tx*4];
            u64 bp[4] = { pack2(b0.x,b0.y), pack2(b0.z,b0.w),
                          pack2(b1.x,b1.y), pack2(b1.z,b1.w) };
            float av[8] = {a0.x,a0.y,a0.z,a0.w,a1.x,a1.y,a1.z,a1.w};
            #pragma unroll
            for (int r = 0; r < 8; r++) {
                u64 ap = pack2(av[r], av[r]);
                #pragma unroll
                for (int j = 0; j < 4; j++) acc[r][j] = fma2(ap, bp[j], acc[r][j]);
            }
        }
    };

    ldg_tile(0);
    sts_tile(0);
    __syncthreads();
    const int KIT = KSUB / 16;
    for (int it = 0; it < KIT; it++) {
        int buf = it & 1;
        bool more = (it + 1 < KIT);
        if (more) ldg_tile((it + 1) * 16);   // LDG in flight over compute
        compute(buf);
        if (more) sts_tile(buf ^ 1);
        __syncthreads();
    }

    // epilogue
    float aa[8] = {0,0,0,0,0,0,0,0};
    if (EPI_G) {
        float4 av0 = *(const float4*)(avec + cb + tx*4);
        float4 av1 = *(const float4*)(avec + cb + 64 + tx*4);
        aa[0]=av0.x; aa[1]=av0.y; aa[2]=av0.z; aa[3]=av0.w;
        aa[4]=av1.x; aa[5]=av1.y; aa[6]=av1.z; aa[7]=av1.w;
    }
    #pragma unroll
    for (int r = 0; r < 8; r++) {
        int m = rb + ty*4 + (r & 3) + ((r >> 2) * 32);
        float2 u0 = unpack2(acc[r][0]), u1 = unpack2(acc[r][1]);
        float2 u2 = unpack2(acc[r][2]), u3 = unpack2(acc[r][3]);
        float o[8] = {u0.x,u0.y,u1.x,u1.y,u2.x,u2.y,u3.x,u3.y};
        if (EPI_G) {
            #pragma unroll
            for (int i = 0; i < 8; i++) {
                float aH = aa[i];
                float s = 1.f - aH * aH;
                o[i] = s * o[i] * (1.f - aH * o[i]);   // s*u + 0.5*(-2a*s)*u^2
            }
        }
        float* Crow = C + (size_t)m * ldc + cb;
        *(float4*)(Crow + tx*4)      = make_float4(o[0],o[1],o[2],o[3]);
        *(float4*)(Crow + 64 + tx*4) = make_float4(o[4],o[5],o[6],o[7]);
    }
}

// ---------------- a = tanh((y + c*kprev) @ W1 + b1) ----------------
// 32 blocks x 256 thr; 4-way d-split + smem reduce; coalesced W1 rows.
__global__ void __launch_bounds__(256) hcalc_kernel(
    const float* __restrict__ y, const float* __restrict__ kprev,
    const float* __restrict__ ts, int interval, float cmul,
    const float* __restrict__ W1, const float* __restrict__ b1,
    float* __restrict__ aout)
{
    __shared__ float ysh[DIM];
    __shared__ float red[256];
    int t = threadIdx.x;
    float dt = (ts[interval+1] - ts[interval]) * (1.0f / SUBSTEPS);
    float c = cmul * dt;
    ysh[t]       = y[t]       + c * kprev[t];
    ysh[t + 256] = y[t + 256] + c * kprev[t + 256];
    __syncthreads();
    int ds = t >> 6;           // 0..3
    int jj = t & 63;
    int j = blockIdx.x * 64 + jj;
    const float* w = W1 + (size_t)(ds * 128) * HID + j;
    float h = 0.f;
    #pragma unroll 8
    for (int d = 0; d < 128; d++) h += ysh[ds*128 + d] * w[(size_t)d * HID];
    red[t] = h;
    __syncthreads();
    if (t < 64) {
        float hh = red[t] + red[t+64] + red[t+128] + red[t+192] + b1[j];
        aout[j] = tanhf(hh);
    }
}

// ---------------- dy = a @ W2 + b2 ----------------
// 16 blocks x 256 thr; 8-way h-split + smem reduce.
__global__ void __launch_bounds__(256) dycalc_kernel(
    const float* __restrict__ avec, const float* __restrict__ W2,
    const float* __restrict__ b2, float* __restrict__ dyout)
{
    __shared__ float red[256];
    int t = threadIdx.x;
    int hs = t >> 5;           // 0..7
    int dd = t & 31;
    int d = blockIdx.x * 32 + dd;
    const float* w  = W2 + (size_t)(hs * 256) * DIM + d;
    const float* av = avec + hs * 256;
    float acc = 0.f;
    #pragma unroll 8
    for (int h = 0; h < 256; h++) acc += av[h] * w[(size_t)h * DIM];
    red[t] = acc;
    __syncthreads();
    if (t < 32) {
        float s = 0.f;
        #pragma unroll
        for (int i = 0; i < 8; i++) s += red[dd + i*32];
        dyout[d] = s + b2[d];
    }
}

// ---------------- RK4 combine: u += dt/6 (k1 + 2k2 + 2k3 + k4) ----------------
// Sums the 4 split-K partials of each kDy inline (deterministic, no atomics).
__global__ void __launch_bounds__(256) combine_kernel(const float* __restrict__ ts, int interval)
{
    int i = blockIdx.x * 256 + threadIdx.x;
    float dt = (ts[interval+1] - ts[interval]) * (1.0f / SUBSTEPS);
    float w = dt * (1.0f / 6.0f);
    if (i < ND) {
        float s = 0.f;
        #pragma unroll
        for (int j = 0; j < 4; j++)
            s += (g_kDy[(size_t)(0*4+j)*ND + i] + g_kDy[(size_t)(3*4+j)*ND + i])
               + 2.f * (g_kDy[(size_t)(1*4+j)*ND + i] + g_kDy[(size_t)(2*4+j)*ND + i]);
        g_Dy[i] += w * s;
    } else if (i < ND + DIM) {
        int d = i - ND;
        g_y[d] += w * (g_kdy[d] + 2.f*g_kdy[DIM + d] + 2.f*g_kdy[2*DIM + d] + g_kdy[3*DIM + d]);
    }
}

// ---------------- driver ----------------
extern "C" void kernel_launch(void* const* d_in, const int* in_sizes, int n_in,
                              void* d_out, int out_size)
{
    (void)in_sizes; (void)n_in; (void)out_size;
    const float* ts  = (const float*)d_in[0];
    const float* y0  = (const float*)d_in[1];
    const float* Dy0 = (const float*)d_in[2];
    const float* W1  = (const float*)d_in[3];
    const float* b1  = (const float*)d_in[4];
    const float* W2  = (const float*)d_in[5];
    const float* b2  = (const float*)d_in[6];
    float* out = (float*)d_out;

    float *y, *Dy, *a, *kdy, *kDy, *G;
    cudaGetSymbolAddress((void**)&y,   g_y);
    cudaGetSymbolAddress((void**)&Dy,  g_Dy);
    cudaGetSymbolAddress((void**)&a,   g_a);
    cudaGetSymbolAddress((void**)&kdy, g_kdy);
    cudaGetSymbolAddress((void**)&kDy, g_kDy);
    cudaGetSymbolAddress((void**)&G,   g_G);

    // init state + t=0 output slice
    cudaMemcpyAsync(y,  y0,  DIM*sizeof(float), cudaMemcpyDeviceToDevice, 0);
    cudaMemcpyAsync(Dy, Dy0, (size_t)ND*sizeof(float), cudaMemcpyDeviceToDevice, 0);
    cudaMemcpyAsync(out, y0, DIM*sizeof(float), cudaMemcpyDeviceToDevice, 0);
    cudaMemcpyAsync(out + DIM, Dy0, (size_t)ND*sizeof(float), cudaMemcpyDeviceToDevice, 0);

    const float CM[4] = {0.f, 0.5f, 0.5f, 1.f};
    for (int interval = 0; interval < NSTEPS; interval++) {
        for (int sub = 0; sub < SUBSTEPS; sub++) {
            for (int s = 0; s < 4; s++) {
                const float* kprev = s ? (kdy + (size_t)(s-1)*DIM) : y;
                hcalc_kernel<<<32, 256>>>(y, kprev, ts, interval, CM[s], W1, b1, a);
                dycalc_kernel<<<16, 256>>>(a, W2, b2, kdy + (size_t)s*DIM);
                if (s == 0) {
                    gemm64x128<false, true><<<dim3(16,8,1), 128>>>(
                        Dy, DIM, nullptr, nullptr, nullptr, nullptr,
                        ts, interval, 0.f, W1, HID, a, G, HID, 0);
                } else {
                    const float* pb = kDy + (size_t)(s-1)*4*ND;
                    gemm64x128<true, true><<<dim3(16,8,1), 128>>>(
                        Dy, DIM, pb, pb + (size_t)ND, pb + 2*(size_t)ND, pb + 3*(size_t)ND,
                        ts, interval, CM[s], W1, HID, a, G, HID, 0);
                }
                gemm64x128<false, false><<<dim3(4,8,4), 128>>>(
                    G, HID, nullptr, nullptr, nullptr, nullptr,
                    ts, interval, 0.f, W2, DIM, nullptr,
                    kDy + (size_t)s*4*ND, DIM, ND);
            }
            combine_kernel<<<(ND + DIM + 255)/256, 256>>>(ts, interval);
        }
        float* dst = out + (size_t)(interval+1) * (1 + NBR) * DIM;
        cudaMemcpyAsync(dst, y, DIM*sizeof(float), cudaMemcpyDeviceToDevice, 0);
        cudaMemcpyAsync(dst + DIM, Dy, (size_t)ND*sizeof(float), cudaMemcpyDeviceToDevice, 0);
    }
}